// round 1
// baseline (speedup 1.0000x reference)
#include <cuda_runtime.h>
#include <math.h>
#include <stdint.h>

// Problem constants
static constexpr int Bc   = 8;
static constexpr int Nn   = 10000;
static constexpr int Ee   = 320000;
static constexpr int HISTc = 24;
static constexpr int PREDc = 12;
static constexpr int TT   = HISTc + PREDc;   // 36
static constexpr int INd  = 17;
static constexpr int GOUT = 13;
static constexpr int HIDc = 64;

// ---------------- device scratch (static, no allocations) ----------------
__device__ __align__(16) float d_hbuf[(long long)Bc * Ee * 32]; // padded edge messages, 327MB
__device__ float d_h[Bc * Nn * HIDc];   // GRU hidden state
__device__ float d_xn[Bc * Nn];         // current node scalar (t2m prediction)
__device__ float d_ea[Ee];              // normalized edge attr
__device__ float d_stats[2];            // sum, sumsq
__device__ int d_deg_t[Nn], d_deg_s[Nn];
__device__ int d_off_t[Nn + 1], d_off_s[Nn + 1];
__device__ int d_cnt_t[Nn], d_cnt_s[Nn];
__device__ int d_perm_t[Ee], d_perm_s[Ee];

// ---------------- helpers ----------------
__device__ __forceinline__ float sigm(float x) {
    return __fdividef(1.0f, 1.0f + __expf(-x));
}
__device__ __forceinline__ float tanh_f(float x) {
    x = fminf(15.0f, fmaxf(-15.0f, x));
    float e = __expf(-2.0f * x);
    return __fdividef(1.0f - e, 1.0f + e);
}

// ---------------- setup kernels ----------------
__global__ void zero_small_kernel() {
    int i = blockIdx.x * blockDim.x + threadIdx.x;
    if (i < 2) d_stats[i] = 0.f;
    if (i < Nn) { d_deg_t[i] = 0; d_deg_s[i] = 0; d_cnt_t[i] = 0; d_cnt_s[i] = 0; }
}

__global__ void zero_h_kernel() {
    int i = blockIdx.x * blockDim.x + threadIdx.x;
    if (i < Bc * Nn * HIDc) d_h[i] = 0.f;
}

__global__ void stats_kernel(const float* __restrict__ ea) {
    __shared__ float ssum[256], ssq[256];
    int t = threadIdx.x;
    int i = blockIdx.x * 256 + t;
    float v = (i < Ee) ? ea[i] : 0.f;
    ssum[t] = v; ssq[t] = v * v;
    __syncthreads();
    for (int s = 128; s > 0; s >>= 1) {
        if (t < s) { ssum[t] += ssum[t + s]; ssq[t] += ssq[t + s]; }
        __syncthreads();
    }
    if (t == 0) {
        atomicAdd(&d_stats[0], ssum[0]);
        atomicAdd(&d_stats[1], ssq[0]);
    }
}

__global__ void eanorm_kernel(const float* __restrict__ ea) {
    int i = blockIdx.x * blockDim.x + threadIdx.x;
    if (i >= Ee) return;
    float s = d_stats[0], sq = d_stats[1];
    float mean = s / (float)Ee;
    float var = (sq - s * s / (float)Ee) / (float)(Ee - 1);
    float inv = rsqrtf(var);
    d_ea[i] = (ea[i] - mean) * inv;
}

__global__ void deg_kernel(const int* __restrict__ ei) {
    int i = blockIdx.x * blockDim.x + threadIdx.x;
    if (i >= Ee) return;
    atomicAdd(&d_deg_s[ei[i]], 1);
    atomicAdd(&d_deg_t[ei[Ee + i]], 1);
}

__global__ void scan_kernel(int which) {
    const int* deg = which ? d_deg_s : d_deg_t;
    int* off = which ? d_off_s : d_off_t;
    __shared__ int part[256];
    const int CH = (Nn + 255) / 256;  // 40
    int t = threadIdx.x;
    int s = 0;
    for (int i = 0; i < CH; i++) {
        int idx = t * CH + i;
        if (idx < Nn) s += deg[idx];
    }
    part[t] = s;
    __syncthreads();
    if (t == 0) {
        int run = 0;
        for (int i = 0; i < 256; i++) { int v = part[i]; part[i] = run; run += v; }
        off[Nn] = run;
    }
    __syncthreads();
    int run = part[t];
    for (int i = 0; i < CH; i++) {
        int idx = t * CH + i;
        if (idx < Nn) { off[idx] = run; run += deg[idx]; }
    }
}

__global__ void fill_kernel(const int* __restrict__ ei) {
    int i = blockIdx.x * blockDim.x + threadIdx.x;
    if (i >= Ee) return;
    int sn = ei[i], tn = ei[Ee + i];
    int p = atomicAdd(&d_cnt_s[sn], 1);
    d_perm_s[d_off_s[sn] + p] = i;
    p = atomicAdd(&d_cnt_t[tn], 1);
    d_perm_t[d_off_t[tn] + p] = i;
}

__global__ void initxn_kernel(const float* __restrict__ t2m) {
    int i = blockIdx.x * blockDim.x + threadIdx.x;
    if (i >= Bc * Nn) return;
    int b = i / Nn, n = i - b * Nn;
    d_xn[i] = t2m[((long long)b * HISTc + (HISTc - 1)) * Nn + n];
}

// ---------------- edge MLP kernel ----------------
// grid: (Ee/128, Bc), 128 threads. one thread per (b,e).
__global__ void __launch_bounds__(128) edge_kernel(
    const int* __restrict__ ei, const float* __restrict__ feat,
    const float* __restrict__ w1, const float* __restrict__ b1,
    const float* __restrict__ w2, const float* __restrict__ b2, int t)
{
    __shared__ float s_w1[35 * 32], s_b1[32], s_w2[32 * 30], s_b2[30];
    for (int i = threadIdx.x; i < 35 * 32; i += 128) s_w1[i] = w1[i];
    for (int i = threadIdx.x; i < 32 * 30; i += 128) s_w2[i] = w2[i];
    if (threadIdx.x < 32) s_b1[threadIdx.x] = b1[threadIdx.x];
    if (threadIdx.x < 30) s_b2[threadIdx.x] = b2[threadIdx.x];
    __syncthreads();

    int e = blockIdx.x * 128 + threadIdx.x;
    int b = blockIdx.y;
    int sn = ei[e], tn = ei[Ee + e];

    float in[35];
    in[0] = d_xn[b * Nn + sn];
    {
        const float4* fs = (const float4*)(feat + ((long long)(b * TT + HISTc + t) * Nn + sn) * 16);
        float4 f0 = fs[0], f1 = fs[1], f2 = fs[2], f3 = fs[3];
        in[1] = f0.x; in[2] = f0.y; in[3] = f0.z; in[4] = f0.w;
        in[5] = f1.x; in[6] = f1.y; in[7] = f1.z; in[8] = f1.w;
        in[9] = f2.x; in[10] = f2.y; in[11] = f2.z; in[12] = f2.w;
        in[13] = f3.x; in[14] = f3.y; in[15] = f3.z; in[16] = f3.w;
    }
    in[17] = d_xn[b * Nn + tn];
    {
        const float4* fs = (const float4*)(feat + ((long long)(b * TT + HISTc + t) * Nn + tn) * 16);
        float4 f0 = fs[0], f1 = fs[1], f2 = fs[2], f3 = fs[3];
        in[18] = f0.x; in[19] = f0.y; in[20] = f0.z; in[21] = f0.w;
        in[22] = f1.x; in[23] = f1.y; in[24] = f1.z; in[25] = f1.w;
        in[26] = f2.x; in[27] = f2.y; in[28] = f2.z; in[29] = f2.w;
        in[30] = f3.x; in[31] = f3.y; in[32] = f3.z; in[33] = f3.w;
    }
    in[34] = d_ea[e];

    float h1[32];
    #pragma unroll
    for (int j = 0; j < 32; j++) h1[j] = s_b1[j];
    #pragma unroll
    for (int k = 0; k < 35; k++) {
        float xk = in[k];
        #pragma unroll
        for (int j = 0; j < 32; j++) h1[j] = fmaf(xk, s_w1[k * 32 + j], h1[j]);
    }
    #pragma unroll
    for (int j = 0; j < 32; j++) h1[j] = sigm(h1[j]);

    float h2[32];
    #pragma unroll
    for (int j = 0; j < 30; j++) h2[j] = s_b2[j];
    h2[30] = 0.f; h2[31] = 0.f;
    #pragma unroll
    for (int k = 0; k < 32; k++) {
        float xk = h1[k];
        #pragma unroll
        for (int j = 0; j < 30; j++) h2[j] = fmaf(xk, s_w2[k * 30 + j], h2[j]);
    }
    #pragma unroll
    for (int j = 0; j < 30; j++) h2[j] = sigm(h2[j]);

    float4* dst = (float4*)(d_hbuf + ((long long)b * Ee + e) * 32);
    #pragma unroll
    for (int q = 0; q < 8; q++)
        dst[q] = make_float4(h2[4 * q], h2[4 * q + 1], h2[4 * q + 2], h2[4 * q + 3]);
}

// ---------------- fused gather + node MLP + GRU + fc_out ----------------
// grid: 10000 blocks x 256 threads (8 warps = 8 rows/block). warp per (b,n).
__global__ void __launch_bounds__(256) step2_kernel(
    const float* __restrict__ feat,
    const float* __restrict__ node_w, const float* __restrict__ node_b,
    const float* __restrict__ wih, const float* __restrict__ whh,
    const float* __restrict__ bih, const float* __restrict__ bhh,
    const float* __restrict__ fcw, const float* __restrict__ fcb,
    float* __restrict__ out, int t)
{
    extern __shared__ float dynw[];
    float* s_wih = dynw;              // [30][192] transposed
    float* s_whh = dynw + 30 * 192;   // [64][192] transposed
    __shared__ float stage[8][96];

    for (int i = threadIdx.x; i < 30 * 192; i += 256) {
        int k = i / 192, r = i - k * 192;
        s_wih[i] = wih[r * 30 + k];
    }
    for (int i = threadIdx.x; i < 64 * 192; i += 256) {
        int k = i / 192, r = i - k * 192;
        s_whh[i] = whh[r * 64 + k];
    }
    __syncthreads();

    int lane = threadIdx.x & 31;
    int w = threadIdx.x >> 5;
    int row = blockIdx.x * 8 + w;
    int b = row / Nn, n = row - b * Nn;
    float* s = stage[w];

    // --- gather agg[lane] (lanes 30,31 accumulate zeros from padding) ---
    float acc = 0.f;
    {
        const float* hb = d_hbuf + (long long)b * Ee * 32;
        int e0 = d_off_t[n], e1 = d_off_t[n + 1];
        for (int i = e0; i < e1; i++)
            acc += hb[(long long)d_perm_t[i] * 32 + lane];
        e0 = d_off_s[n]; e1 = d_off_s[n + 1];
        for (int i = e0; i < e1; i++)
            acc -= hb[(long long)d_perm_s[i] * 32 + lane];
    }
    s[lane] = acc;
    float x0 = d_xn[row];
    __syncwarp();

    // --- build xin = [g(13), xn(1), feat(16)] in s[64..93] ---
    if (lane < 13) {
        float g = node_b[lane];
        #pragma unroll
        for (int k = 0; k < 30; k++) g = fmaf(s[k], node_w[k * 13 + lane], g);
        s[64 + lane] = sigm(g);
    } else if (lane == 13) {
        s[64 + 13] = x0;
    } else if (lane < 30) {
        s[64 + lane] = feat[((long long)(b * TT + HISTc + t) * Nn + n) * 16 + (lane - 14)];
    }
    __syncwarp();

    // --- load old h into s[0..63] ---
    float hold0 = d_h[(long long)row * 64 + lane];
    float hold1 = d_h[(long long)row * 64 + 32 + lane];
    s[lane] = hold0;
    s[32 + lane] = hold1;
    __syncwarp();

    // --- GRU: lane handles hidden units (lane) and (lane+32) ---
    float a0r = bih[lane],       a1r = bih[32 + lane];
    float a0z = bih[64 + lane],  a1z = bih[96 + lane];
    float a0n = bih[128 + lane], a1n = bih[160 + lane];
    #pragma unroll
    for (int k = 0; k < 30; k++) {
        float xk = s[64 + k];
        const float* wr = s_wih + k * 192;
        a0r = fmaf(xk, wr[lane], a0r);
        a1r = fmaf(xk, wr[32 + lane], a1r);
        a0z = fmaf(xk, wr[64 + lane], a0z);
        a1z = fmaf(xk, wr[96 + lane], a1z);
        a0n = fmaf(xk, wr[128 + lane], a0n);
        a1n = fmaf(xk, wr[160 + lane], a1n);
    }
    float g0r = bhh[lane],       g1r = bhh[32 + lane];
    float g0z = bhh[64 + lane],  g1z = bhh[96 + lane];
    float g0n = bhh[128 + lane], g1n = bhh[160 + lane];
    #pragma unroll
    for (int k = 0; k < 64; k++) {
        float hk = s[k];
        const float* wr = s_whh + k * 192;
        g0r = fmaf(hk, wr[lane], g0r);
        g1r = fmaf(hk, wr[32 + lane], g1r);
        g0z = fmaf(hk, wr[64 + lane], g0z);
        g1z = fmaf(hk, wr[96 + lane], g1z);
        g0n = fmaf(hk, wr[128 + lane], g0n);
        g1n = fmaf(hk, wr[160 + lane], g1n);
    }
    float r0 = sigm(a0r + g0r), r1 = sigm(a1r + g1r);
    float z0 = sigm(a0z + g0z), z1 = sigm(a1z + g1z);
    float nn0 = tanh_f(a0n + r0 * g0n), nn1 = tanh_f(a1n + r1 * g1n);
    float hn0 = (1.f - z0) * nn0 + z0 * hold0;
    float hn1 = (1.f - z1) * nn1 + z1 * hold1;

    d_h[(long long)row * 64 + lane] = hn0;
    d_h[(long long)row * 64 + 32 + lane] = hn1;

    float o = hn0 * fcw[lane] + hn1 * fcw[32 + lane];
    #pragma unroll
    for (int off = 16; off > 0; off >>= 1)
        o += __shfl_xor_sync(0xffffffffu, o, off);
    if (lane == 0) {
        float v = o + fcb[0];
        d_xn[row] = v;
        out[((long long)b * PREDc + t) * Nn + n] = v;
    }
}

// ---------------- launcher ----------------
extern "C" void kernel_launch(void* const* d_in, const int* in_sizes, int n_in,
                              void* d_out, int out_size)
{
    const float* t2m  = (const float*)d_in[0];
    const float* feat = (const float*)d_in[1];
    const int*   ei   = (const int*)d_in[2];
    const float* ea   = (const float*)d_in[3];
    const float* w1   = (const float*)d_in[4];
    const float* b1   = (const float*)d_in[5];
    const float* w2   = (const float*)d_in[6];
    const float* b2   = (const float*)d_in[7];
    const float* nw   = (const float*)d_in[8];
    const float* nb   = (const float*)d_in[9];
    const float* wih  = (const float*)d_in[10];
    const float* whh  = (const float*)d_in[11];
    const float* bih  = (const float*)d_in[12];
    const float* bhh  = (const float*)d_in[13];
    const float* fcw  = (const float*)d_in[14];
    const float* fcb  = (const float*)d_in[15];
    float* out = (float*)d_out;

    static bool attr_set = false;
    // cudaFuncSetAttribute is idempotent and stream-free; call every time (no work skipped).
    (void)attr_set;
    cudaFuncSetAttribute(step2_kernel, cudaFuncAttributeMaxDynamicSharedMemorySize,
                         (30 * 192 + 64 * 192) * (int)sizeof(float));

    const int EB = (Ee + 255) / 256;        // 1250

    zero_small_kernel<<<(Nn + 255) / 256, 256>>>();
    zero_h_kernel<<<(Bc * Nn * HIDc + 255) / 256, 256>>>();
    stats_kernel<<<EB, 256>>>(ea);
    eanorm_kernel<<<EB, 256>>>(ea);
    deg_kernel<<<EB, 256>>>(ei);
    scan_kernel<<<1, 256>>>(0);
    scan_kernel<<<1, 256>>>(1);
    fill_kernel<<<EB, 256>>>(ei);
    initxn_kernel<<<(Bc * Nn + 255) / 256, 256>>>(t2m);

    dim3 egrid(Ee / 128, Bc);
    const int smem2 = (30 * 192 + 64 * 192) * (int)sizeof(float);
    for (int t = 0; t < PREDc; t++) {
        edge_kernel<<<egrid, 128>>>(ei, feat, w1, b1, w2, b2, t);
        step2_kernel<<<10000, 256, smem2>>>(feat, nw, nb, wih, whh, bih, bhh, fcw, fcb, out, t);
    }
}

// round 2
// speedup vs baseline: 1.0954x; 1.0954x over previous
#include <cuda_runtime.h>
#include <math.h>
#include <stdint.h>

// Problem constants
static constexpr int Bc   = 8;
static constexpr int Nn   = 10000;
static constexpr int Ee   = 320000;
static constexpr int HISTc = 24;
static constexpr int PREDc = 12;
static constexpr int TT   = HISTc + PREDc;   // 36
static constexpr int HIDc = 64;

// ---------------- device scratch (static, no allocations) ----------------
__device__ __align__(16) float d_hbuf[(long long)Bc * Ee * 32]; // edge messages, tgt-sorted order
__device__ float d_h[Bc * Nn * HIDc];   // GRU hidden state
__device__ float d_xn[Bc * Nn];         // current node scalar
__device__ float d_ea[Ee];              // normalized edge attr (original order)
__device__ float d_stats[2];
__device__ int d_deg_t[Nn], d_deg_s[Nn];
__device__ int d_off_t[Nn + 1], d_off_s[Nn + 1];
__device__ int d_cnt_t[Nn], d_cnt_s[Nn];
__device__ int d_perm_t[Ee], d_perm_s[Ee];
__device__ int d_invt[Ee];              // original edge -> t-order slot
__device__ int d_slot_s[Ee];            // src-order i -> t-order slot
__device__ int d_src_t[Ee], d_tgt_t[Ee];// node ids in t-order
__device__ float d_ea_t[Ee];            // edge attr in t-order

// ---------------- helpers ----------------
__device__ __forceinline__ float sigm(float x) {
    return __fdividef(1.0f, 1.0f + __expf(-x));
}
__device__ __forceinline__ float tanh_f(float x) {
    x = fminf(15.0f, fmaxf(-15.0f, x));
    float e = __expf(-2.0f * x);
    return __fdividef(1.0f - e, 1.0f + e);
}
__device__ __forceinline__ unsigned long long splat2(float x) {
    unsigned long long r;
    asm("mov.b64 %0, {%1, %1};" : "=l"(r) : "f"(x));
    return r;
}
__device__ __forceinline__ void fma2(unsigned long long& d, unsigned long long a, unsigned long long b) {
    asm("fma.rn.f32x2 %0, %1, %2, %0;" : "+l"(d) : "l"(a), "l"(b));
}
__device__ __forceinline__ float2 unpack2(unsigned long long v) {
    float2 f;
    asm("mov.b64 {%0, %1}, %2;" : "=f"(f.x), "=f"(f.y) : "l"(v));
    return f;
}

// ---------------- setup kernels ----------------
__global__ void zero_small_kernel() {
    int i = blockIdx.x * blockDim.x + threadIdx.x;
    if (i < 2) d_stats[i] = 0.f;
    if (i < Nn) { d_deg_t[i] = 0; d_deg_s[i] = 0; d_cnt_t[i] = 0; d_cnt_s[i] = 0; }
}

__global__ void zero_h_kernel() {
    int i = blockIdx.x * blockDim.x + threadIdx.x;
    if (i < Bc * Nn * HIDc) d_h[i] = 0.f;
}

__global__ void stats_kernel(const float* __restrict__ ea) {
    __shared__ float ssum[256], ssq[256];
    int t = threadIdx.x;
    int i = blockIdx.x * 256 + t;
    float v = (i < Ee) ? ea[i] : 0.f;
    ssum[t] = v; ssq[t] = v * v;
    __syncthreads();
    for (int s = 128; s > 0; s >>= 1) {
        if (t < s) { ssum[t] += ssum[t + s]; ssq[t] += ssq[t + s]; }
        __syncthreads();
    }
    if (t == 0) {
        atomicAdd(&d_stats[0], ssum[0]);
        atomicAdd(&d_stats[1], ssq[0]);
    }
}

__global__ void eanorm_kernel(const float* __restrict__ ea) {
    int i = blockIdx.x * blockDim.x + threadIdx.x;
    if (i >= Ee) return;
    float s = d_stats[0], sq = d_stats[1];
    float mean = s / (float)Ee;
    float var = (sq - s * s / (float)Ee) / (float)(Ee - 1);
    float inv = rsqrtf(var);
    d_ea[i] = (ea[i] - mean) * inv;
}

__global__ void deg_kernel(const int* __restrict__ ei) {
    int i = blockIdx.x * blockDim.x + threadIdx.x;
    if (i >= Ee) return;
    atomicAdd(&d_deg_s[ei[i]], 1);
    atomicAdd(&d_deg_t[ei[Ee + i]], 1);
}

__global__ void scan_kernel(int which) {
    const int* deg = which ? d_deg_s : d_deg_t;
    int* off = which ? d_off_s : d_off_t;
    __shared__ int part[256];
    const int CH = (Nn + 255) / 256;
    int t = threadIdx.x;
    int s = 0;
    for (int i = 0; i < CH; i++) {
        int idx = t * CH + i;
        if (idx < Nn) s += deg[idx];
    }
    part[t] = s;
    __syncthreads();
    if (t == 0) {
        int run = 0;
        for (int i = 0; i < 256; i++) { int v = part[i]; part[i] = run; run += v; }
        off[Nn] = run;
    }
    __syncthreads();
    int run = part[t];
    for (int i = 0; i < CH; i++) {
        int idx = t * CH + i;
        if (idx < Nn) { off[idx] = run; run += deg[idx]; }
    }
}

__global__ void fill_kernel(const int* __restrict__ ei) {
    int i = blockIdx.x * blockDim.x + threadIdx.x;
    if (i >= Ee) return;
    int sn = ei[i], tn = ei[Ee + i];
    int p = atomicAdd(&d_cnt_s[sn], 1);
    d_perm_s[d_off_s[sn] + p] = i;
    p = atomicAdd(&d_cnt_t[tn], 1);
    d_perm_t[d_off_t[tn] + p] = i;
}

__global__ void reorder_kernel(const int* __restrict__ ei) {
    int idx = blockIdx.x * blockDim.x + threadIdx.x;
    if (idx >= Ee) return;
    int e = d_perm_t[idx];
    d_src_t[idx] = ei[e];
    d_tgt_t[idx] = ei[Ee + e];
    d_ea_t[idx]  = d_ea[e];
    d_invt[e]    = idx;
}

__global__ void slot_kernel() {
    int i = blockIdx.x * blockDim.x + threadIdx.x;
    if (i >= Ee) return;
    d_slot_s[i] = d_invt[d_perm_s[i]];
}

__global__ void initxn_kernel(const float* __restrict__ t2m) {
    int i = blockIdx.x * blockDim.x + threadIdx.x;
    if (i >= Bc * Nn) return;
    int b = i / Nn, n = i - b * Nn;
    d_xn[i] = t2m[((long long)b * HISTc + (HISTc - 1)) * Nn + n];
}

// ---------------- edge MLP kernel (FFMA2 packed, t-sorted output) ----------------
// grid: (Ee/128, Bc), 128 threads. one thread per (b, t-order slot).
__global__ void __launch_bounds__(128) edge_kernel(
    const float* __restrict__ feat,
    const float* __restrict__ w1, const float* __restrict__ b1,
    const float* __restrict__ w2, const float* __restrict__ b2, int t)
{
    __shared__ __align__(16) float s_w1[35 * 32];
    __shared__ __align__(16) float s_b1[32];
    __shared__ __align__(16) float s_w2[32 * 30];
    __shared__ __align__(16) float s_b2[30];
    for (int i = threadIdx.x; i < 35 * 32; i += 128) s_w1[i] = w1[i];
    for (int i = threadIdx.x; i < 32 * 30; i += 128) s_w2[i] = w2[i];
    if (threadIdx.x < 32) s_b1[threadIdx.x] = b1[threadIdx.x];
    if (threadIdx.x < 30) s_b2[threadIdx.x] = b2[threadIdx.x];
    __syncthreads();

    int idx = blockIdx.x * 128 + threadIdx.x;
    int b = blockIdx.y;
    int sn = d_src_t[idx], tn = d_tgt_t[idx];

    float in[35];
    in[0] = d_xn[b * Nn + sn];
    {
        const float4* fs = (const float4*)(feat + ((long long)(b * TT + HISTc + t) * Nn + sn) * 16);
        float4 f0 = fs[0], f1 = fs[1], f2 = fs[2], f3 = fs[3];
        in[1] = f0.x; in[2] = f0.y; in[3] = f0.z; in[4] = f0.w;
        in[5] = f1.x; in[6] = f1.y; in[7] = f1.z; in[8] = f1.w;
        in[9] = f2.x; in[10] = f2.y; in[11] = f2.z; in[12] = f2.w;
        in[13] = f3.x; in[14] = f3.y; in[15] = f3.z; in[16] = f3.w;
    }
    in[17] = d_xn[b * Nn + tn];
    {
        const float4* fs = (const float4*)(feat + ((long long)(b * TT + HISTc + t) * Nn + tn) * 16);
        float4 f0 = fs[0], f1 = fs[1], f2 = fs[2], f3 = fs[3];
        in[18] = f0.x; in[19] = f0.y; in[20] = f0.z; in[21] = f0.w;
        in[22] = f1.x; in[23] = f1.y; in[24] = f1.z; in[25] = f1.w;
        in[26] = f2.x; in[27] = f2.y; in[28] = f2.z; in[29] = f2.w;
        in[30] = f3.x; in[31] = f3.y; in[32] = f3.z; in[33] = f3.w;
    }
    in[34] = d_ea_t[idx];

    // ---- layer 1: 35 -> 32, packed pairs ----
    unsigned long long acc1[16];
    {
        const unsigned long long* bp = (const unsigned long long*)s_b1;
        #pragma unroll
        for (int j = 0; j < 16; j++) acc1[j] = bp[j];
    }
    {
        const unsigned long long* wp = (const unsigned long long*)s_w1;
        #pragma unroll
        for (int k = 0; k < 35; k++) {
            unsigned long long xk = splat2(in[k]);
            #pragma unroll
            for (int j = 0; j < 16; j++) fma2(acc1[j], xk, wp[k * 16 + j]);
        }
    }
    float h1[32];
    #pragma unroll
    for (int j = 0; j < 16; j++) {
        float2 f = unpack2(acc1[j]);
        h1[2 * j] = sigm(f.x);
        h1[2 * j + 1] = sigm(f.y);
    }

    // ---- layer 2: 32 -> 30, packed pairs ----
    unsigned long long acc2[15];
    {
        const unsigned long long* bp = (const unsigned long long*)s_b2;
        #pragma unroll
        for (int j = 0; j < 15; j++) acc2[j] = bp[j];
    }
    {
        const unsigned long long* wp = (const unsigned long long*)s_w2;
        #pragma unroll
        for (int k = 0; k < 32; k++) {
            unsigned long long xk = splat2(h1[k]);
            #pragma unroll
            for (int j = 0; j < 15; j++) fma2(acc2[j], xk, wp[k * 15 + j]);
        }
    }
    float h2[32];
    #pragma unroll
    for (int j = 0; j < 15; j++) {
        float2 f = unpack2(acc2[j]);
        h2[2 * j] = sigm(f.x);
        h2[2 * j + 1] = sigm(f.y);
    }
    h2[30] = 0.f; h2[31] = 0.f;

    float4* dst = (float4*)(d_hbuf + ((long long)b * Ee + idx) * 32);
    #pragma unroll
    for (int q = 0; q < 8; q++)
        dst[q] = make_float4(h2[4 * q], h2[4 * q + 1], h2[4 * q + 2], h2[4 * q + 3]);
}

// ---------------- fused gather + node MLP + GRU + fc_out ----------------
// grid: 10000 blocks x 256 threads (8 warps). warp per (b,n).
__global__ void __launch_bounds__(256) step2_kernel(
    const float* __restrict__ feat,
    const float* __restrict__ node_w, const float* __restrict__ node_b,
    const float* __restrict__ wih, const float* __restrict__ whh,
    const float* __restrict__ bih, const float* __restrict__ bhh,
    const float* __restrict__ fcw, const float* __restrict__ fcb,
    float* __restrict__ out, int t)
{
    extern __shared__ float dynw[];
    float* s_wih = dynw;              // [30][192] transposed
    float* s_whh = dynw + 30 * 192;   // [64][192] transposed
    __shared__ float stage[8][96];

    for (int i = threadIdx.x; i < 30 * 192; i += 256) {
        int k = i / 192, r = i - k * 192;
        s_wih[i] = wih[r * 30 + k];
    }
    for (int i = threadIdx.x; i < 64 * 192; i += 256) {
        int k = i / 192, r = i - k * 192;
        s_whh[i] = whh[r * 64 + k];
    }
    __syncthreads();

    int lane = threadIdx.x & 31;
    int w = threadIdx.x >> 5;
    int row = blockIdx.x * 8 + w;
    int b = row / Nn, n = row - b * Nn;
    float* s = stage[w];

    // --- gather agg[lane] (lanes 30,31 see zero padding) ---
    float acc = 0.f;
    {
        const float* hb = d_hbuf + (long long)b * Ee * 32;
        // tgt: contiguous stream
        int e0 = d_off_t[n], e1 = d_off_t[n + 1];
        const float* p = hb + (long long)e0 * 32 + lane;
        int cnt = e1 - e0;
        int i = 0;
        for (; i + 4 <= cnt; i += 4) {
            float v0 = p[(long long)(i) * 32];
            float v1 = p[(long long)(i + 1) * 32];
            float v2 = p[(long long)(i + 2) * 32];
            float v3 = p[(long long)(i + 3) * 32];
            acc += (v0 + v1) + (v2 + v3);
        }
        for (; i < cnt; i++) acc += p[(long long)i * 32];

        // src: random via slot map, unroll 8 for MLP
        e0 = d_off_s[n]; e1 = d_off_s[n + 1];
        i = e0;
        for (; i + 8 <= e1; i += 8) {
            int s0 = d_slot_s[i],     s1 = d_slot_s[i + 1];
            int s2 = d_slot_s[i + 2], s3 = d_slot_s[i + 3];
            int s4 = d_slot_s[i + 4], s5 = d_slot_s[i + 5];
            int s6 = d_slot_s[i + 6], s7 = d_slot_s[i + 7];
            float v0 = hb[(long long)s0 * 32 + lane];
            float v1 = hb[(long long)s1 * 32 + lane];
            float v2 = hb[(long long)s2 * 32 + lane];
            float v3 = hb[(long long)s3 * 32 + lane];
            float v4 = hb[(long long)s4 * 32 + lane];
            float v5 = hb[(long long)s5 * 32 + lane];
            float v6 = hb[(long long)s6 * 32 + lane];
            float v7 = hb[(long long)s7 * 32 + lane];
            acc -= ((v0 + v1) + (v2 + v3)) + ((v4 + v5) + (v6 + v7));
        }
        for (; i < e1; i++) acc -= hb[(long long)d_slot_s[i] * 32 + lane];
    }
    s[lane] = acc;
    float x0 = d_xn[row];
    __syncwarp();

    // --- build xin = [g(13), xn(1), feat(16)] in s[64..93] ---
    if (lane < 13) {
        float g = node_b[lane];
        #pragma unroll
        for (int k = 0; k < 30; k++) g = fmaf(s[k], node_w[k * 13 + lane], g);
        s[64 + lane] = sigm(g);
    } else if (lane == 13) {
        s[64 + 13] = x0;
    } else if (lane < 30) {
        s[64 + lane] = feat[((long long)(b * TT + HISTc + t) * Nn + n) * 16 + (lane - 14)];
    }
    __syncwarp();

    // --- load old h into s[0..63] ---
    float hold0 = d_h[(long long)row * 64 + lane];
    float hold1 = d_h[(long long)row * 64 + 32 + lane];
    s[lane] = hold0;
    s[32 + lane] = hold1;
    __syncwarp();

    // --- GRU: lane handles hidden units (lane) and (lane+32) ---
    float a0r = bih[lane],       a1r = bih[32 + lane];
    float a0z = bih[64 + lane],  a1z = bih[96 + lane];
    float a0n = bih[128 + lane], a1n = bih[160 + lane];
    #pragma unroll
    for (int k = 0; k < 30; k++) {
        float xk = s[64 + k];
        const float* wr = s_wih + k * 192;
        a0r = fmaf(xk, wr[lane], a0r);
        a1r = fmaf(xk, wr[32 + lane], a1r);
        a0z = fmaf(xk, wr[64 + lane], a0z);
        a1z = fmaf(xk, wr[96 + lane], a1z);
        a0n = fmaf(xk, wr[128 + lane], a0n);
        a1n = fmaf(xk, wr[160 + lane], a1n);
    }
    float g0r = bhh[lane],       g1r = bhh[32 + lane];
    float g0z = bhh[64 + lane],  g1z = bhh[96 + lane];
    float g0n = bhh[128 + lane], g1n = bhh[160 + lane];
    #pragma unroll
    for (int k = 0; k < 64; k++) {
        float hk = s[k];
        const float* wr = s_whh + k * 192;
        g0r = fmaf(hk, wr[lane], g0r);
        g1r = fmaf(hk, wr[32 + lane], g1r);
        g0z = fmaf(hk, wr[64 + lane], g0z);
        g1z = fmaf(hk, wr[96 + lane], g1z);
        g0n = fmaf(hk, wr[128 + lane], g0n);
        g1n = fmaf(hk, wr[160 + lane], g1n);
    }
    float r0 = sigm(a0r + g0r), r1 = sigm(a1r + g1r);
    float z0 = sigm(a0z + g0z), z1 = sigm(a1z + g1z);
    float nn0 = tanh_f(a0n + r0 * g0n), nn1 = tanh_f(a1n + r1 * g1n);
    float hn0 = (1.f - z0) * nn0 + z0 * hold0;
    float hn1 = (1.f - z1) * nn1 + z1 * hold1;

    d_h[(long long)row * 64 + lane] = hn0;
    d_h[(long long)row * 64 + 32 + lane] = hn1;

    float o = hn0 * fcw[lane] + hn1 * fcw[32 + lane];
    #pragma unroll
    for (int off = 16; off > 0; off >>= 1)
        o += __shfl_xor_sync(0xffffffffu, o, off);
    if (lane == 0) {
        float v = o + fcb[0];
        d_xn[row] = v;
        out[((long long)b * PREDc + t) * Nn + n] = v;
    }
}

// ---------------- launcher ----------------
extern "C" void kernel_launch(void* const* d_in, const int* in_sizes, int n_in,
                              void* d_out, int out_size)
{
    const float* t2m  = (const float*)d_in[0];
    const float* feat = (const float*)d_in[1];
    const int*   ei   = (const int*)d_in[2];
    const float* ea   = (const float*)d_in[3];
    const float* w1   = (const float*)d_in[4];
    const float* b1   = (const float*)d_in[5];
    const float* w2   = (const float*)d_in[6];
    const float* b2   = (const float*)d_in[7];
    const float* nw   = (const float*)d_in[8];
    const float* nb   = (const float*)d_in[9];
    const float* wih  = (const float*)d_in[10];
    const float* whh  = (const float*)d_in[11];
    const float* bih  = (const float*)d_in[12];
    const float* bhh  = (const float*)d_in[13];
    const float* fcw  = (const float*)d_in[14];
    const float* fcb  = (const float*)d_in[15];
    float* out = (float*)d_out;

    cudaFuncSetAttribute(step2_kernel, cudaFuncAttributeMaxDynamicSharedMemorySize,
                         (30 * 192 + 64 * 192) * (int)sizeof(float));

    const int EB = (Ee + 255) / 256;

    zero_small_kernel<<<(Nn + 255) / 256, 256>>>();
    zero_h_kernel<<<(Bc * Nn * HIDc + 255) / 256, 256>>>();
    stats_kernel<<<EB, 256>>>(ea);
    eanorm_kernel<<<EB, 256>>>(ea);
    deg_kernel<<<EB, 256>>>(ei);
    scan_kernel<<<1, 256>>>(0);
    scan_kernel<<<1, 256>>>(1);
    fill_kernel<<<EB, 256>>>(ei);
    reorder_kernel<<<EB, 256>>>(ei);
    slot_kernel<<<EB, 256>>>();
    initxn_kernel<<<(Bc * Nn + 255) / 256, 256>>>(t2m);

    dim3 egrid(Ee / 128, Bc);
    const int smem2 = (30 * 192 + 64 * 192) * (int)sizeof(float);
    for (int t = 0; t < PREDc; t++) {
        edge_kernel<<<egrid, 128>>>(feat, w1, b1, w2, b2, t);
        step2_kernel<<<10000, 256, smem2>>>(feat, nw, nb, wih, whh, bih, bhh, fcw, fcb, out, t);
    }
}

// round 3
// speedup vs baseline: 2.0616x; 1.8820x over previous
#include <cuda_runtime.h>
#include <math.h>
#include <stdint.h>

// Problem constants
static constexpr int Bc   = 8;
static constexpr int Nn   = 10000;
static constexpr int Ee   = 320000;
static constexpr int HISTc = 24;
static constexpr int PREDc = 12;
static constexpr int TT   = HISTc + PREDc;   // 36
static constexpr int HIDc = 64;

// ---------------- device scratch (static, no allocations) ----------------
__device__ __align__(16) float d_hbuf[(long long)Bc * Ee * 32]; // edge messages, tgt-sorted order
__device__ float d_h[Bc * Nn * HIDc];   // GRU hidden state
__device__ float d_xn[Bc * Nn];         // current node scalar
__device__ float d_ea[Ee];              // normalized edge attr (original order)
__device__ float d_stats[2];
__device__ int d_deg_t[Nn], d_deg_s[Nn];
__device__ int d_off_t[Nn + 1], d_off_s[Nn + 1];
__device__ int d_cnt_t[Nn], d_cnt_s[Nn];
__device__ int d_perm_s[Ee];
__device__ int d_invt[Ee];              // original edge -> t-order slot
__device__ int d_slot_s[Ee];            // src-order i -> t-order slot
__device__ int d_src_t[Ee], d_tgt_t[Ee];// node ids in t-order
__device__ float d_ea_t[Ee];            // edge attr in t-order
__device__ __align__(16) float d_wihT[30 * 192];  // transposed GRU input weights
__device__ __align__(16) float d_whhT[64 * 192];  // transposed GRU hidden weights

// ---------------- helpers ----------------
__device__ __forceinline__ float sigm(float x) {
    return __fdividef(1.0f, 1.0f + __expf(-x));
}
__device__ __forceinline__ float tanh_f(float x) {
    x = fminf(15.0f, fmaxf(-15.0f, x));
    float e = __expf(-2.0f * x);
    return __fdividef(1.0f - e, 1.0f + e);
}
__device__ __forceinline__ unsigned long long splat2(float x) {
    unsigned long long r;
    asm("mov.b64 %0, {%1, %1};" : "=l"(r) : "f"(x));
    return r;
}
__device__ __forceinline__ void fma2(unsigned long long& d, unsigned long long a, unsigned long long b) {
    asm("fma.rn.f32x2 %0, %1, %2, %0;" : "+l"(d) : "l"(a), "l"(b));
}
__device__ __forceinline__ float2 unpack2(unsigned long long v) {
    float2 f;
    asm("mov.b64 {%0, %1}, %2;" : "=f"(f.x), "=f"(f.y) : "l"(v));
    return f;
}

// ---------------- setup kernels (5 total, fused) ----------------
// K1: zero everything + init xn
__global__ void k1_zero_init(const float* __restrict__ t2m) {
    int i = blockIdx.x * blockDim.x + threadIdx.x;
    if (i < 2) d_stats[i] = 0.f;
    if (i < Nn) { d_deg_t[i] = 0; d_deg_s[i] = 0; d_cnt_t[i] = 0; d_cnt_s[i] = 0; }
    if (i < Bc * Nn) {
        int b = i / Nn, n = i - b * Nn;
        d_xn[i] = t2m[((long long)b * HISTc + (HISTc - 1)) * Nn + n];
    }
    for (long long j = i; j < (long long)Bc * Nn * HIDc; j += (long long)gridDim.x * blockDim.x)
        d_h[j] = 0.f;
}

// K2: edge-attr stats + degree histogram
__global__ void k2_stats_deg(const float* __restrict__ ea, const int* __restrict__ ei) {
    __shared__ float ssum[256], ssq[256];
    int t = threadIdx.x;
    int i = blockIdx.x * 256 + t;
    float v = 0.f;
    if (i < Ee) {
        v = ea[i];
        atomicAdd(&d_deg_s[ei[i]], 1);
        atomicAdd(&d_deg_t[ei[Ee + i]], 1);
    }
    ssum[t] = v; ssq[t] = v * v;
    __syncthreads();
    for (int s = 128; s > 0; s >>= 1) {
        if (t < s) { ssum[t] += ssum[t + s]; ssq[t] += ssq[t + s]; }
        __syncthreads();
    }
    if (t == 0) {
        atomicAdd(&d_stats[0], ssum[0]);
        atomicAdd(&d_stats[1], ssq[0]);
    }
}

// K3: normalize ea (blocks >=2) + exclusive scans (blocks 0,1)
__global__ void k3_norm_scan(const float* __restrict__ ea) {
    if (blockIdx.x < 2) {
        int which = blockIdx.x;
        const int* deg = which ? d_deg_s : d_deg_t;
        int* off = which ? d_off_s : d_off_t;
        __shared__ int part[256];
        const int CH = (Nn + 255) / 256;
        int t = threadIdx.x;
        int s = 0;
        for (int i = 0; i < CH; i++) {
            int idx = t * CH + i;
            if (idx < Nn) s += deg[idx];
        }
        part[t] = s;
        __syncthreads();
        if (t == 0) {
            int run = 0;
            for (int i = 0; i < 256; i++) { int vv = part[i]; part[i] = run; run += vv; }
            off[Nn] = run;
        }
        __syncthreads();
        int run = part[t];
        for (int i = 0; i < CH; i++) {
            int idx = t * CH + i;
            if (idx < Nn) { off[idx] = run; run += deg[idx]; }
        }
        return;
    }
    int i = (blockIdx.x - 2) * blockDim.x + threadIdx.x;
    if (i >= Ee) return;
    float s = d_stats[0], sq = d_stats[1];
    float mean = s / (float)Ee;
    float var = (sq - s * s / (float)Ee) / (float)(Ee - 1);
    float inv = rsqrtf(var);
    d_ea[i] = (ea[i] - mean) * inv;
}

// K4: fill + direct reorder (computes invt, src_t/tgt_t/ea_t in place)
__global__ void k4_fill(const int* __restrict__ ei) {
    int e = blockIdx.x * blockDim.x + threadIdx.x;
    if (e >= Ee) return;
    int sn = ei[e], tn = ei[Ee + e];
    int p = atomicAdd(&d_cnt_s[sn], 1);
    d_perm_s[d_off_s[sn] + p] = e;
    p = atomicAdd(&d_cnt_t[tn], 1);
    int slot = d_off_t[tn] + p;
    d_invt[e] = slot;
    d_src_t[slot] = sn;
    d_tgt_t[slot] = tn;
    d_ea_t[slot] = d_ea[e];
}

// K5: slot map + weight transpose
__global__ void k5_slot_transpose(const float* __restrict__ wih, const float* __restrict__ whh) {
    int i = blockIdx.x * blockDim.x + threadIdx.x;
    if (i < Ee) d_slot_s[i] = d_invt[d_perm_s[i]];
    if (i < 30 * 192) {
        int k = i / 192, r = i - k * 192;
        d_wihT[i] = wih[r * 30 + k];
    }
    if (i < 64 * 192) {
        int k = i / 192, r = i - k * 192;
        d_whhT[i] = whh[r * 64 + k];
    }
}

// ---------------- edge MLP kernel (FFMA2 packed, t-sorted output) ----------------
// grid: (Ee/128, Bc), 128 threads. one thread per (b, t-order slot).
__global__ void __launch_bounds__(128) edge_kernel(
    const float* __restrict__ feat,
    const float* __restrict__ w1, const float* __restrict__ b1,
    const float* __restrict__ w2, const float* __restrict__ b2, int t)
{
    __shared__ __align__(16) float s_w1[35 * 32];
    __shared__ __align__(16) float s_b1[32];
    __shared__ __align__(16) float s_w2[32 * 30];
    __shared__ __align__(16) float s_b2[30];
    for (int i = threadIdx.x; i < 35 * 32; i += 128) s_w1[i] = w1[i];
    for (int i = threadIdx.x; i < 32 * 30; i += 128) s_w2[i] = w2[i];
    if (threadIdx.x < 32) s_b1[threadIdx.x] = b1[threadIdx.x];
    if (threadIdx.x < 30) s_b2[threadIdx.x] = b2[threadIdx.x];
    __syncthreads();

    int idx = blockIdx.x * 128 + threadIdx.x;
    int b = blockIdx.y;
    int sn = d_src_t[idx], tn = d_tgt_t[idx];

    float in[35];
    in[0] = d_xn[b * Nn + sn];
    {
        const float4* fs = (const float4*)(feat + ((long long)(b * TT + HISTc + t) * Nn + sn) * 16);
        float4 f0 = fs[0], f1 = fs[1], f2 = fs[2], f3 = fs[3];
        in[1] = f0.x; in[2] = f0.y; in[3] = f0.z; in[4] = f0.w;
        in[5] = f1.x; in[6] = f1.y; in[7] = f1.z; in[8] = f1.w;
        in[9] = f2.x; in[10] = f2.y; in[11] = f2.z; in[12] = f2.w;
        in[13] = f3.x; in[14] = f3.y; in[15] = f3.z; in[16] = f3.w;
    }
    in[17] = d_xn[b * Nn + tn];
    {
        const float4* fs = (const float4*)(feat + ((long long)(b * TT + HISTc + t) * Nn + tn) * 16);
        float4 f0 = fs[0], f1 = fs[1], f2 = fs[2], f3 = fs[3];
        in[18] = f0.x; in[19] = f0.y; in[20] = f0.z; in[21] = f0.w;
        in[22] = f1.x; in[23] = f1.y; in[24] = f1.z; in[25] = f1.w;
        in[26] = f2.x; in[27] = f2.y; in[28] = f2.z; in[29] = f2.w;
        in[30] = f3.x; in[31] = f3.y; in[32] = f3.z; in[33] = f3.w;
    }
    in[34] = d_ea_t[idx];

    // ---- layer 1: 35 -> 32, packed pairs ----
    unsigned long long acc1[16];
    {
        const unsigned long long* bp = (const unsigned long long*)s_b1;
        #pragma unroll
        for (int j = 0; j < 16; j++) acc1[j] = bp[j];
    }
    {
        const unsigned long long* wp = (const unsigned long long*)s_w1;
        #pragma unroll
        for (int k = 0; k < 35; k++) {
            unsigned long long xk = splat2(in[k]);
            #pragma unroll
            for (int j = 0; j < 16; j++) fma2(acc1[j], xk, wp[k * 16 + j]);
        }
    }
    float h1[32];
    #pragma unroll
    for (int j = 0; j < 16; j++) {
        float2 f = unpack2(acc1[j]);
        h1[2 * j] = sigm(f.x);
        h1[2 * j + 1] = sigm(f.y);
    }

    // ---- layer 2: 32 -> 30, packed pairs ----
    unsigned long long acc2[15];
    {
        const unsigned long long* bp = (const unsigned long long*)s_b2;
        #pragma unroll
        for (int j = 0; j < 15; j++) acc2[j] = bp[j];
    }
    {
        const unsigned long long* wp = (const unsigned long long*)s_w2;
        #pragma unroll
        for (int k = 0; k < 32; k++) {
            unsigned long long xk = splat2(h1[k]);
            #pragma unroll
            for (int j = 0; j < 15; j++) fma2(acc2[j], xk, wp[k * 15 + j]);
        }
    }
    float h2[32];
    #pragma unroll
    for (int j = 0; j < 15; j++) {
        float2 f = unpack2(acc2[j]);
        h2[2 * j] = sigm(f.x);
        h2[2 * j + 1] = sigm(f.y);
    }
    h2[30] = 0.f; h2[31] = 0.f;

    float4* dst = (float4*)(d_hbuf + ((long long)b * Ee + idx) * 32);
    #pragma unroll
    for (int q = 0; q < 8; q++)
        dst[q] = make_float4(h2[4 * q], h2[4 * q + 1], h2[4 * q + 2], h2[4 * q + 3]);
}

// ---------------- persistent fused gather + node MLP + GRU + fc_out ----------------
// grid: 296 blocks x 512 threads (16 warps). warp processes rows in strides.
static constexpr int S2_BLOCKS = 296;
static constexpr int S2_WARPS  = 16;

__global__ void __launch_bounds__(512) step2_kernel(
    const float* __restrict__ feat,
    const float* __restrict__ node_w, const float* __restrict__ node_b,
    const float* __restrict__ bih, const float* __restrict__ bhh,
    const float* __restrict__ fcw, const float* __restrict__ fcb,
    float* __restrict__ out, int t)
{
    extern __shared__ float dynw[];
    float* s_wih = dynw;              // [30][192] transposed
    float* s_whh = dynw + 30 * 192;   // [64][192] transposed
    __shared__ float stage[S2_WARPS][96];

    // coalesced fill from pre-transposed buffers (once per block)
    for (int i = threadIdx.x; i < 30 * 192; i += 512) s_wih[i] = d_wihT[i];
    for (int i = threadIdx.x; i < 64 * 192; i += 512) s_whh[i] = d_whhT[i];
    __syncthreads();

    int lane = threadIdx.x & 31;
    int w = threadIdx.x >> 5;
    float* s = stage[w];

    for (int row = blockIdx.x * S2_WARPS + w; row < Bc * Nn; row += S2_BLOCKS * S2_WARPS) {
        int b = row / Nn, n = row - b * Nn;

        // --- gather agg[lane] (lanes 30,31 see zero padding) ---
        float acc = 0.f;
        {
            const float* hb = d_hbuf + (long long)b * Ee * 32;
            // tgt: contiguous stream
            int e0 = d_off_t[n], e1 = d_off_t[n + 1];
            const float* p = hb + (long long)e0 * 32 + lane;
            int cnt = e1 - e0;
            int i = 0;
            for (; i + 4 <= cnt; i += 4) {
                float v0 = p[(long long)(i) * 32];
                float v1 = p[(long long)(i + 1) * 32];
                float v2 = p[(long long)(i + 2) * 32];
                float v3 = p[(long long)(i + 3) * 32];
                acc += (v0 + v1) + (v2 + v3);
            }
            for (; i < cnt; i++) acc += p[(long long)i * 32];

            // src: random via slot map, unroll 8 for MLP
            e0 = d_off_s[n]; e1 = d_off_s[n + 1];
            i = e0;
            for (; i + 8 <= e1; i += 8) {
                int s0 = d_slot_s[i],     s1 = d_slot_s[i + 1];
                int s2 = d_slot_s[i + 2], s3 = d_slot_s[i + 3];
                int s4 = d_slot_s[i + 4], s5 = d_slot_s[i + 5];
                int s6 = d_slot_s[i + 6], s7 = d_slot_s[i + 7];
                float v0 = hb[(long long)s0 * 32 + lane];
                float v1 = hb[(long long)s1 * 32 + lane];
                float v2 = hb[(long long)s2 * 32 + lane];
                float v3 = hb[(long long)s3 * 32 + lane];
                float v4 = hb[(long long)s4 * 32 + lane];
                float v5 = hb[(long long)s5 * 32 + lane];
                float v6 = hb[(long long)s6 * 32 + lane];
                float v7 = hb[(long long)s7 * 32 + lane];
                acc -= ((v0 + v1) + (v2 + v3)) + ((v4 + v5) + (v6 + v7));
            }
            for (; i < e1; i++) acc -= hb[(long long)d_slot_s[i] * 32 + lane];
        }
        s[lane] = acc;
        float x0 = d_xn[row];
        __syncwarp();

        // --- build xin = [g(13), xn(1), feat(16)] in s[64..93] ---
        if (lane < 13) {
            float g = node_b[lane];
            #pragma unroll
            for (int k = 0; k < 30; k++) g = fmaf(s[k], node_w[k * 13 + lane], g);
            s[64 + lane] = sigm(g);
        } else if (lane == 13) {
            s[64 + 13] = x0;
        } else if (lane < 30) {
            s[64 + lane] = feat[((long long)(b * TT + HISTc + t) * Nn + n) * 16 + (lane - 14)];
        }
        __syncwarp();

        // --- load old h into s[0..63] ---
        float hold0 = d_h[(long long)row * 64 + lane];
        float hold1 = d_h[(long long)row * 64 + 32 + lane];
        s[lane] = hold0;
        s[32 + lane] = hold1;
        __syncwarp();

        // --- GRU: lane handles hidden units (lane) and (lane+32) ---
        float a0r = bih[lane],       a1r = bih[32 + lane];
        float a0z = bih[64 + lane],  a1z = bih[96 + lane];
        float a0n = bih[128 + lane], a1n = bih[160 + lane];
        #pragma unroll
        for (int k = 0; k < 30; k++) {
            float xk = s[64 + k];
            const float* wr = s_wih + k * 192;
            a0r = fmaf(xk, wr[lane], a0r);
            a1r = fmaf(xk, wr[32 + lane], a1r);
            a0z = fmaf(xk, wr[64 + lane], a0z);
            a1z = fmaf(xk, wr[96 + lane], a1z);
            a0n = fmaf(xk, wr[128 + lane], a0n);
            a1n = fmaf(xk, wr[160 + lane], a1n);
        }
        float g0r = bhh[lane],       g1r = bhh[32 + lane];
        float g0z = bhh[64 + lane],  g1z = bhh[96 + lane];
        float g0n = bhh[128 + lane], g1n = bhh[160 + lane];
        #pragma unroll
        for (int k = 0; k < 64; k++) {
            float hk = s[k];
            const float* wr = s_whh + k * 192;
            g0r = fmaf(hk, wr[lane], g0r);
            g1r = fmaf(hk, wr[32 + lane], g1r);
            g0z = fmaf(hk, wr[64 + lane], g0z);
            g1z = fmaf(hk, wr[96 + lane], g1z);
            g0n = fmaf(hk, wr[128 + lane], g0n);
            g1n = fmaf(hk, wr[160 + lane], g1n);
        }
        float r0 = sigm(a0r + g0r), r1 = sigm(a1r + g1r);
        float z0 = sigm(a0z + g0z), z1 = sigm(a1z + g1z);
        float nn0 = tanh_f(a0n + r0 * g0n), nn1 = tanh_f(a1n + r1 * g1n);
        float hn0 = (1.f - z0) * nn0 + z0 * hold0;
        float hn1 = (1.f - z1) * nn1 + z1 * hold1;

        d_h[(long long)row * 64 + lane] = hn0;
        d_h[(long long)row * 64 + 32 + lane] = hn1;

        float o = hn0 * fcw[lane] + hn1 * fcw[32 + lane];
        #pragma unroll
        for (int off = 16; off > 0; off >>= 1)
            o += __shfl_xor_sync(0xffffffffu, o, off);
        if (lane == 0) {
            float v = o + fcb[0];
            d_xn[row] = v;
            out[((long long)b * PREDc + t) * Nn + n] = v;
        }
        __syncwarp();
    }
}

// ---------------- launcher ----------------
extern "C" void kernel_launch(void* const* d_in, const int* in_sizes, int n_in,
                              void* d_out, int out_size)
{
    const float* t2m  = (const float*)d_in[0];
    const float* feat = (const float*)d_in[1];
    const int*   ei   = (const int*)d_in[2];
    const float* ea   = (const float*)d_in[3];
    const float* w1   = (const float*)d_in[4];
    const float* b1   = (const float*)d_in[5];
    const float* w2   = (const float*)d_in[6];
    const float* b2   = (const float*)d_in[7];
    const float* nw   = (const float*)d_in[8];
    const float* nb   = (const float*)d_in[9];
    const float* wih  = (const float*)d_in[10];
    const float* whh  = (const float*)d_in[11];
    const float* bih  = (const float*)d_in[12];
    const float* bhh  = (const float*)d_in[13];
    const float* fcw  = (const float*)d_in[14];
    const float* fcb  = (const float*)d_in[15];
    float* out = (float*)d_out;

    const int smem2 = (30 * 192 + 64 * 192) * (int)sizeof(float);
    cudaFuncSetAttribute(step2_kernel, cudaFuncAttributeMaxDynamicSharedMemorySize, smem2);

    const int EB = (Ee + 255) / 256;

    k1_zero_init<<<(Bc * Nn + 255) / 256, 256>>>(t2m);
    k2_stats_deg<<<EB, 256>>>(ea, ei);
    k3_norm_scan<<<EB + 2, 256>>>(ea);
    k4_fill<<<EB, 256>>>(ei);
    k5_slot_transpose<<<EB, 256>>>(wih, whh);

    dim3 egrid(Ee / 128, Bc);
    for (int t = 0; t < PREDc; t++) {
        edge_kernel<<<egrid, 128>>>(feat, w1, b1, w2, b2, t);
        step2_kernel<<<S2_BLOCKS, 512, smem2>>>(feat, nw, nb, bih, bhh, fcw, fcb, out, t);
    }
}

// round 4
// speedup vs baseline: 2.2546x; 1.0936x over previous
#include <cuda_runtime.h>
#include <cuda_fp16.h>
#include <math.h>
#include <stdint.h>

// Problem constants
static constexpr int Bc   = 8;
static constexpr int Nn   = 10000;
static constexpr int Ee   = 320000;
static constexpr int HISTc = 24;
static constexpr int PREDc = 12;
static constexpr int TT   = HISTc + PREDc;   // 36
static constexpr int HIDc = 64;

// ---------------- device scratch (static, no allocations) ----------------
__device__ __align__(16) __half d_hbuf_t[(long long)Bc * Ee * 32]; // messages, tgt-sorted
__device__ __align__(16) __half d_hbuf_s[(long long)Bc * Ee * 32]; // messages, src-sorted
__device__ float d_h[Bc * Nn * HIDc];   // GRU hidden state
__device__ float d_xn[Bc * Nn];         // current node scalar
__device__ float d_ea[Ee];              // normalized edge attr (original order)
__device__ float d_stats[2];
__device__ int d_deg_t[Nn], d_deg_s[Nn];
__device__ int d_off_t[Nn + 1], d_off_s[Nn + 1];
__device__ int d_cnt_t[Nn], d_cnt_s[Nn];
__device__ int d_sslot_t[Ee];           // t-order slot -> s-order slot
__device__ int d_src_t[Ee], d_tgt_t[Ee];// node ids in t-order
__device__ float d_ea_t[Ee];            // edge attr in t-order
__device__ __align__(16) float2 d_wihT2[30 * 96];  // paired GRU input weights
__device__ __align__(16) float2 d_whhT2[64 * 96];  // paired GRU hidden weights

// ---------------- helpers ----------------
__device__ __forceinline__ float sigm(float x) {
    return __fdividef(1.0f, 1.0f + __expf(-x));
}
__device__ __forceinline__ float tanh_f(float x) {
    x = fminf(15.0f, fmaxf(-15.0f, x));
    float e = __expf(-2.0f * x);
    return __fdividef(1.0f - e, 1.0f + e);
}
__device__ __forceinline__ unsigned long long splat2(float x) {
    unsigned long long r;
    asm("mov.b64 %0, {%1, %1};" : "=l"(r) : "f"(x));
    return r;
}
__device__ __forceinline__ unsigned long long pack2(float lo, float hi) {
    unsigned long long r;
    asm("mov.b64 %0, {%1, %2};" : "=l"(r) : "f"(lo), "f"(hi));
    return r;
}
__device__ __forceinline__ void fma2(unsigned long long& d, unsigned long long a, unsigned long long b) {
    asm("fma.rn.f32x2 %0, %1, %2, %0;" : "+l"(d) : "l"(a), "l"(b));
}
__device__ __forceinline__ float2 unpack2(unsigned long long v) {
    float2 f;
    asm("mov.b64 {%0, %1}, %2;" : "=f"(f.x), "=f"(f.y) : "l"(v));
    return f;
}

// ---------------- setup kernels ----------------
// K1: zero everything + init xn
__global__ void k1_zero_init(const float* __restrict__ t2m) {
    int i = blockIdx.x * blockDim.x + threadIdx.x;
    if (i < 2) d_stats[i] = 0.f;
    if (i < Nn) { d_deg_t[i] = 0; d_deg_s[i] = 0; d_cnt_t[i] = 0; d_cnt_s[i] = 0; }
    if (i < Bc * Nn) {
        int b = i / Nn, n = i - b * Nn;
        d_xn[i] = t2m[((long long)b * HISTc + (HISTc - 1)) * Nn + n];
    }
    for (long long j = i; j < (long long)Bc * Nn * HIDc; j += (long long)gridDim.x * blockDim.x)
        d_h[j] = 0.f;
}

// K2: edge-attr stats + degree histogram
__global__ void k2_stats_deg(const float* __restrict__ ea, const int* __restrict__ ei) {
    __shared__ float ssum[256], ssq[256];
    int t = threadIdx.x;
    int i = blockIdx.x * 256 + t;
    float v = 0.f;
    if (i < Ee) {
        v = ea[i];
        atomicAdd(&d_deg_s[ei[i]], 1);
        atomicAdd(&d_deg_t[ei[Ee + i]], 1);
    }
    ssum[t] = v; ssq[t] = v * v;
    __syncthreads();
    for (int s = 128; s > 0; s >>= 1) {
        if (t < s) { ssum[t] += ssum[t + s]; ssq[t] += ssq[t + s]; }
        __syncthreads();
    }
    if (t == 0) {
        atomicAdd(&d_stats[0], ssum[0]);
        atomicAdd(&d_stats[1], ssq[0]);
    }
}

// K3: normalize ea (blocks >=2) + exclusive scans (blocks 0,1)
__global__ void k3_norm_scan(const float* __restrict__ ea) {
    if (blockIdx.x < 2) {
        int which = blockIdx.x;
        const int* deg = which ? d_deg_s : d_deg_t;
        int* off = which ? d_off_s : d_off_t;
        __shared__ int part[256];
        const int CH = (Nn + 255) / 256;
        int t = threadIdx.x;
        int s = 0;
        for (int i = 0; i < CH; i++) {
            int idx = t * CH + i;
            if (idx < Nn) s += deg[idx];
        }
        part[t] = s;
        __syncthreads();
        if (t == 0) {
            int run = 0;
            for (int i = 0; i < 256; i++) { int vv = part[i]; part[i] = run; run += vv; }
            off[Nn] = run;
        }
        __syncthreads();
        int run = part[t];
        for (int i = 0; i < CH; i++) {
            int idx = t * CH + i;
            if (idx < Nn) { off[idx] = run; run += deg[idx]; }
        }
        return;
    }
    int i = (blockIdx.x - 2) * blockDim.x + threadIdx.x;
    if (i >= Ee) return;
    float s = d_stats[0], sq = d_stats[1];
    float mean = s / (float)Ee;
    float var = (sq - s * s / (float)Ee) / (float)(Ee - 1);
    float inv = rsqrtf(var);
    d_ea[i] = (ea[i] - mean) * inv;
}

// K4: fill t-order tables + t->s slot map
__global__ void k4_fill(const int* __restrict__ ei) {
    int e = blockIdx.x * blockDim.x + threadIdx.x;
    if (e >= Ee) return;
    int sn = ei[e], tn = ei[Ee + e];
    int ps = atomicAdd(&d_cnt_s[sn], 1);
    int sslot = d_off_s[sn] + ps;
    int pt = atomicAdd(&d_cnt_t[tn], 1);
    int tslot = d_off_t[tn] + pt;
    d_sslot_t[tslot] = sslot;
    d_src_t[tslot] = sn;
    d_tgt_t[tslot] = tn;
    d_ea_t[tslot] = d_ea[e];
}

// K5: GRU weight pairing (unit j paired with unit j+32, per gate)
__global__ void k5_pack_weights(const float* __restrict__ wih, const float* __restrict__ whh) {
    int i = blockIdx.x * blockDim.x + threadIdx.x;
    if (i < 30 * 96) {
        int k = i / 96, c = i - k * 96;
        int g = c / 32, j = c - g * 32;
        d_wihT2[i] = make_float2(wih[(g * 64 + j) * 30 + k], wih[(g * 64 + 32 + j) * 30 + k]);
    }
    if (i < 64 * 96) {
        int k = i / 96, c = i - k * 96;
        int g = c / 32, j = c - g * 32;
        d_whhT2[i] = make_float2(whh[(g * 64 + j) * 64 + k], whh[(g * 64 + 32 + j) * 64 + k]);
    }
}

// ---------------- edge MLP kernel (FFMA2 packed, fp16 dual-sorted output) ----------------
// grid: (Ee/128, Bc), 128 threads. one thread per (b, t-order slot).
__global__ void __launch_bounds__(128) edge_kernel(
    const float* __restrict__ feat,
    const float* __restrict__ w1, const float* __restrict__ b1,
    const float* __restrict__ w2, const float* __restrict__ b2, int t)
{
    __shared__ __align__(16) float s_w1[35 * 32];
    __shared__ __align__(16) float s_b1[32];
    __shared__ __align__(16) float s_w2[32 * 30];
    __shared__ __align__(16) float s_b2[30];
    for (int i = threadIdx.x; i < 35 * 32; i += 128) s_w1[i] = w1[i];
    for (int i = threadIdx.x; i < 32 * 30; i += 128) s_w2[i] = w2[i];
    if (threadIdx.x < 32) s_b1[threadIdx.x] = b1[threadIdx.x];
    if (threadIdx.x < 30) s_b2[threadIdx.x] = b2[threadIdx.x];
    __syncthreads();

    int idx = blockIdx.x * 128 + threadIdx.x;
    int b = blockIdx.y;
    int sn = d_src_t[idx], tn = d_tgt_t[idx];
    int ss = d_sslot_t[idx];

    float in[35];
    in[0] = d_xn[b * Nn + sn];
    {
        const float4* fs = (const float4*)(feat + ((long long)(b * TT + HISTc + t) * Nn + sn) * 16);
        float4 f0 = fs[0], f1 = fs[1], f2 = fs[2], f3 = fs[3];
        in[1] = f0.x; in[2] = f0.y; in[3] = f0.z; in[4] = f0.w;
        in[5] = f1.x; in[6] = f1.y; in[7] = f1.z; in[8] = f1.w;
        in[9] = f2.x; in[10] = f2.y; in[11] = f2.z; in[12] = f2.w;
        in[13] = f3.x; in[14] = f3.y; in[15] = f3.z; in[16] = f3.w;
    }
    in[17] = d_xn[b * Nn + tn];
    {
        const float4* fs = (const float4*)(feat + ((long long)(b * TT + HISTc + t) * Nn + tn) * 16);
        float4 f0 = fs[0], f1 = fs[1], f2 = fs[2], f3 = fs[3];
        in[18] = f0.x; in[19] = f0.y; in[20] = f0.z; in[21] = f0.w;
        in[22] = f1.x; in[23] = f1.y; in[24] = f1.z; in[25] = f1.w;
        in[26] = f2.x; in[27] = f2.y; in[28] = f2.z; in[29] = f2.w;
        in[30] = f3.x; in[31] = f3.y; in[32] = f3.z; in[33] = f3.w;
    }
    in[34] = d_ea_t[idx];

    // ---- layer 1: 35 -> 32, packed pairs ----
    unsigned long long acc1[16];
    {
        const unsigned long long* bp = (const unsigned long long*)s_b1;
        #pragma unroll
        for (int j = 0; j < 16; j++) acc1[j] = bp[j];
    }
    {
        const unsigned long long* wp = (const unsigned long long*)s_w1;
        #pragma unroll
        for (int k = 0; k < 35; k++) {
            unsigned long long xk = splat2(in[k]);
            #pragma unroll
            for (int j = 0; j < 16; j++) fma2(acc1[j], xk, wp[k * 16 + j]);
        }
    }
    float h1[32];
    #pragma unroll
    for (int j = 0; j < 16; j++) {
        float2 f = unpack2(acc1[j]);
        h1[2 * j] = sigm(f.x);
        h1[2 * j + 1] = sigm(f.y);
    }

    // ---- layer 2: 32 -> 30, packed pairs ----
    unsigned long long acc2[15];
    {
        const unsigned long long* bp = (const unsigned long long*)s_b2;
        #pragma unroll
        for (int j = 0; j < 15; j++) acc2[j] = bp[j];
    }
    {
        const unsigned long long* wp = (const unsigned long long*)s_w2;
        #pragma unroll
        for (int k = 0; k < 32; k++) {
            unsigned long long xk = splat2(h1[k]);
            #pragma unroll
            for (int j = 0; j < 15; j++) fma2(acc2[j], xk, wp[k * 15 + j]);
        }
    }

    // ---- sigmoid + fp16 pack (channels 30,31 zero) ----
    uint32_t hp[16];
    #pragma unroll
    for (int j = 0; j < 15; j++) {
        float2 f = unpack2(acc2[j]);
        __half2 h = __floats2half2_rn(sigm(f.x), sigm(f.y));
        hp[j] = *(uint32_t*)&h;
    }
    hp[15] = 0u;

    const uint4* hpv = (const uint4*)hp;
    uint4* dt = (uint4*)(d_hbuf_t + ((long long)b * Ee + idx) * 32);
    uint4* ds = (uint4*)(d_hbuf_s + ((long long)b * Ee + ss) * 32);
    #pragma unroll
    for (int q = 0; q < 4; q++) dt[q] = hpv[q];
    #pragma unroll
    for (int q = 0; q < 4; q++) ds[q] = hpv[q];
}

// ---------------- persistent fused gather + node MLP + GRU + fc_out ----------------
static constexpr int S2_BLOCKS = 296;
static constexpr int S2_WARPS  = 16;

__global__ void __launch_bounds__(512) step2_kernel(
    const float* __restrict__ feat,
    const float* __restrict__ node_w, const float* __restrict__ node_b,
    const float* __restrict__ bih, const float* __restrict__ bhh,
    const float* __restrict__ fcw, const float* __restrict__ fcb,
    float* __restrict__ out, int t)
{
    extern __shared__ float dynw[];
    float2* s_wih2 = (float2*)dynw;                 // [30][96] pairs
    float2* s_whh2 = (float2*)(dynw + 30 * 96 * 2); // [64][96] pairs
    __shared__ float stage[S2_WARPS][96];
    __shared__ float s_nw[30 * 13], s_nb[13];

    for (int i = threadIdx.x; i < 30 * 96; i += 512) s_wih2[i] = d_wihT2[i];
    for (int i = threadIdx.x; i < 64 * 96; i += 512) s_whh2[i] = d_whhT2[i];
    for (int i = threadIdx.x; i < 30 * 13; i += 512) s_nw[i] = node_w[i];
    if (threadIdx.x < 13) s_nb[threadIdx.x] = node_b[threadIdx.x];
    __syncthreads();

    int lane = threadIdx.x & 31;
    int w = threadIdx.x >> 5;
    float* s = stage[w];

    // hoisted per-lane constants
    unsigned long long bih_r = pack2(bih[lane],       bih[32 + lane]);
    unsigned long long bih_z = pack2(bih[64 + lane],  bih[96 + lane]);
    unsigned long long bih_n = pack2(bih[128 + lane], bih[160 + lane]);
    unsigned long long bhh_r = pack2(bhh[lane],       bhh[32 + lane]);
    unsigned long long bhh_z = pack2(bhh[64 + lane],  bhh[96 + lane]);
    unsigned long long bhh_n = pack2(bhh[128 + lane], bhh[160 + lane]);
    float fcw0 = fcw[lane], fcw1 = fcw[32 + lane];
    float fcb0 = fcb[0];

    for (int row = blockIdx.x * S2_WARPS + w; row < Bc * Nn; row += S2_BLOCKS * S2_WARPS) {
        int b = row / Nn, n = row - b * Nn;

        // --- gather agg[lane]: both streams contiguous ---
        float acc = 0.f;
        {
            // + tgt stream
            int e0 = d_off_t[n], e1 = d_off_t[n + 1];
            const __half* p = d_hbuf_t + ((long long)b * Ee + e0) * 32 + lane;
            int cnt = e1 - e0;
            int i = 0;
            for (; i + 4 <= cnt; i += 4) {
                float v0 = __half2float(p[(long long)(i) * 32]);
                float v1 = __half2float(p[(long long)(i + 1) * 32]);
                float v2 = __half2float(p[(long long)(i + 2) * 32]);
                float v3 = __half2float(p[(long long)(i + 3) * 32]);
                acc += (v0 + v1) + (v2 + v3);
            }
            for (; i < cnt; i++) acc += __half2float(p[(long long)i * 32]);
            // - src stream
            e0 = d_off_s[n]; e1 = d_off_s[n + 1];
            p = d_hbuf_s + ((long long)b * Ee + e0) * 32 + lane;
            cnt = e1 - e0;
            i = 0;
            for (; i + 4 <= cnt; i += 4) {
                float v0 = __half2float(p[(long long)(i) * 32]);
                float v1 = __half2float(p[(long long)(i + 1) * 32]);
                float v2 = __half2float(p[(long long)(i + 2) * 32]);
                float v3 = __half2float(p[(long long)(i + 3) * 32]);
                acc -= (v0 + v1) + (v2 + v3);
            }
            for (; i < cnt; i++) acc -= __half2float(p[(long long)i * 32]);
        }
        s[lane] = acc;
        float x0 = d_xn[row];
        __syncwarp();

        // --- build xin = [g(13), xn(1), feat(16)] in s[64..93] ---
        if (lane < 13) {
            float g = s_nb[lane];
            #pragma unroll
            for (int k = 0; k < 30; k++) g = fmaf(s[k], s_nw[k * 13 + lane], g);
            s[64 + lane] = sigm(g);
        } else if (lane == 13) {
            s[64 + 13] = x0;
        } else if (lane < 30) {
            s[64 + lane] = feat[((long long)(b * TT + HISTc + t) * Nn + n) * 16 + (lane - 14)];
        }
        __syncwarp();

        // --- load old h into s[0..63] ---
        float hold0 = d_h[(long long)row * 64 + lane];
        float hold1 = d_h[(long long)row * 64 + 32 + lane];
        s[lane] = hold0;
        s[32 + lane] = hold1;
        __syncwarp();

        // --- GRU with paired FFMA2 ---
        unsigned long long ar = bih_r, az = bih_z, an = bih_n;
        #pragma unroll
        for (int k = 0; k < 30; k++) {
            unsigned long long xk = splat2(s[64 + k]);
            const unsigned long long* wr = (const unsigned long long*)(s_wih2 + k * 96);
            fma2(ar, xk, wr[lane]);
            fma2(az, xk, wr[32 + lane]);
            fma2(an, xk, wr[64 + lane]);
        }
        unsigned long long gr = bhh_r, gz = bhh_z, gn = bhh_n;
        #pragma unroll
        for (int k = 0; k < 64; k++) {
            unsigned long long hk = splat2(s[k]);
            const unsigned long long* wr = (const unsigned long long*)(s_whh2 + k * 96);
            fma2(gr, hk, wr[lane]);
            fma2(gz, hk, wr[32 + lane]);
            fma2(gn, hk, wr[64 + lane]);
        }
        float2 far = unpack2(ar), faz = unpack2(az), fan = unpack2(an);
        float2 fgr = unpack2(gr), fgz = unpack2(gz), fgn = unpack2(gn);

        float r0 = sigm(far.x + fgr.x), r1 = sigm(far.y + fgr.y);
        float z0 = sigm(faz.x + fgz.x), z1 = sigm(faz.y + fgz.y);
        float nn0 = tanh_f(fan.x + r0 * fgn.x), nn1 = tanh_f(fan.y + r1 * fgn.y);
        float hn0 = (1.f - z0) * nn0 + z0 * hold0;
        float hn1 = (1.f - z1) * nn1 + z1 * hold1;

        d_h[(long long)row * 64 + lane] = hn0;
        d_h[(long long)row * 64 + 32 + lane] = hn1;

        float o = hn0 * fcw0 + hn1 * fcw1;
        #pragma unroll
        for (int off = 16; off > 0; off >>= 1)
            o += __shfl_xor_sync(0xffffffffu, o, off);
        if (lane == 0) {
            float v = o + fcb0;
            d_xn[row] = v;
            out[((long long)b * PREDc + t) * Nn + n] = v;
        }
        __syncwarp();
    }
}

// ---------------- launcher ----------------
extern "C" void kernel_launch(void* const* d_in, const int* in_sizes, int n_in,
                              void* d_out, int out_size)
{
    const float* t2m  = (const float*)d_in[0];
    const float* feat = (const float*)d_in[1];
    const int*   ei   = (const int*)d_in[2];
    const float* ea   = (const float*)d_in[3];
    const float* w1   = (const float*)d_in[4];
    const float* b1   = (const float*)d_in[5];
    const float* w2   = (const float*)d_in[6];
    const float* b2   = (const float*)d_in[7];
    const float* nw   = (const float*)d_in[8];
    const float* nb   = (const float*)d_in[9];
    const float* wih  = (const float*)d_in[10];
    const float* whh  = (const float*)d_in[11];
    const float* bih  = (const float*)d_in[12];
    const float* bhh  = (const float*)d_in[13];
    const float* fcw  = (const float*)d_in[14];
    const float* fcb  = (const float*)d_in[15];
    float* out = (float*)d_out;

    const int smem2 = (30 * 96 + 64 * 96) * 2 * (int)sizeof(float);
    cudaFuncSetAttribute(step2_kernel, cudaFuncAttributeMaxDynamicSharedMemorySize, smem2);

    const int EB = (Ee + 255) / 256;

    k1_zero_init<<<(Bc * Nn + 255) / 256, 256>>>(t2m);
    k2_stats_deg<<<EB, 256>>>(ea, ei);
    k3_norm_scan<<<EB + 2, 256>>>(ea);
    k4_fill<<<EB, 256>>>(ei);
    k5_pack_weights<<<(64 * 96 + 255) / 256, 256>>>(wih, whh);

    dim3 egrid(Ee / 128, Bc);
    for (int t = 0; t < PREDc; t++) {
        edge_kernel<<<egrid, 128>>>(feat, w1, b1, w2, b2, t);
        step2_kernel<<<S2_BLOCKS, 512, smem2>>>(feat, nw, nb, bih, bhh, fcw, fcb, out, t);
    }
}